// round 3
// baseline (speedup 1.0000x reference)
#include <cuda_runtime.h>
#include <cstdint>

#define CHN 512
#define TT 8
#define HH 32
#define WW 32
#define SS 8192            // TT*HH*WW
#define PTD 10             // padded T (2 front)
#define PHD 34             // padded H
#define PWD 34             // padded W
#define PLANE (PTD*PHD*PWD)   // 11560
#define GN_GROUPS 32
#define GN_GSIZE 16        // CHN/GN_GROUPS
#define EPSV 1e-6f

// ---------------- static scratch (no allocations allowed) ----------------
__device__ float g_bufA[CHN*SS];
__device__ float g_bufB[CHN*SS];
__device__ float g_bufC[CHN*SS];
__device__ float g_bufD[CHN*SS];
__device__ float g_bufE[CHN*SS];
__device__ float g_pad[CHN*PLANE];
__device__ float g_P[(size_t)SS*SS];        // 256 MB attention matrix
__device__ float g_wt[27*CHN*CHN];          // repacked conv weight [tap][ci][co]
__device__ float g_wl[CHN*CHN];             // transposed linear weight [c][o]

// ---------------- GroupNorm (+ optional SiLU) ----------------
__global__ void gn_kernel(const float* __restrict__ x, const float* __restrict__ sc,
                          const float* __restrict__ bi, float* __restrict__ y,
                          int do_silu)
{
    int g = blockIdx.x;                     // 32 groups
    const int n = GN_GSIZE * SS;            // 131072
    const float* xg = x + (size_t)g * n;
    double s0 = 0.0, s1 = 0.0;
    for (int i = threadIdx.x; i < n; i += 256) {
        float v = xg[i];
        s0 += (double)v;
        s1 += (double)v * (double)v;
    }
    __shared__ double sh0[256], sh1[256];
    sh0[threadIdx.x] = s0; sh1[threadIdx.x] = s1;
    __syncthreads();
    for (int o = 128; o > 0; o >>= 1) {
        if (threadIdx.x < o) {
            sh0[threadIdx.x] += sh0[threadIdx.x + o];
            sh1[threadIdx.x] += sh1[threadIdx.x + o];
        }
        __syncthreads();
    }
    double mu = sh0[0] / n;
    double var = sh1[0] / n - mu * mu;
    float mean = (float)mu;
    float rstd = rsqrtf((float)var + EPSV);
    float* yg = y + (size_t)g * n;
    for (int i = threadIdx.x; i < n; i += 256) {
        int c = g * GN_GSIZE + (i >> 13);   // i / SS
        float v = (xg[i] - mean) * rstd * sc[c] + bi[c];
        if (do_silu) v = v / (1.f + __expf(-v));
        yg[i] = v;
    }
}

// ---------------- replicate pad (CausalConv3d: t pad (2,0), h/w pad (1,1), edge) ----
__global__ void pad_kernel(const float* __restrict__ x, float* __restrict__ xp)
{
    int idx = blockIdx.x * blockDim.x + threadIdx.x;
    const int total = CHN * PLANE;
    if (idx >= total) return;
    int c  = idx / PLANE;
    int r  = idx % PLANE;
    int tp = r / (PHD * PWD);
    int r2 = r % (PHD * PWD);
    int hp = r2 / PWD;
    int wp = r2 % PWD;
    int t = tp - 2; if (t < 0) t = 0; if (t > TT-1) t = TT-1;
    int h = hp - 1; if (h < 0) h = 0; if (h > HH-1) h = HH-1;
    int w = wp - 1; if (w < 0) w = 0; if (w > WW-1) w = WW-1;
    xp[idx] = x[((size_t)(c * TT + t) * HH + h) * WW + w];
}

// ---------------- conv weight repack: wt[(tap*CHN+ci)*CHN+co] = w[(co*CHN+ci)*27+tap]
__global__ void repack_conv(const float* __restrict__ w, float* __restrict__ wt)
{
    int idx = blockIdx.x * blockDim.x + threadIdx.x;
    const int total = 27 * CHN * CHN;
    if (idx >= total) return;
    int co = idx % CHN;
    int r  = idx / CHN;
    int ci = r % CHN;
    int k  = r / CHN;
    wt[idx] = w[((size_t)co * CHN + ci) * 27 + k];
}

// ---------------- 512x512 transpose: wt[c*CHN+o] = w[o*CHN+c]
__global__ void transpose_lin(const float* __restrict__ w, float* __restrict__ wt)
{
    __shared__ float tile[32][33];
    int bx = blockIdx.x * 32, by = blockIdx.y * 32;
    tile[threadIdx.y][threadIdx.x] = w[(size_t)(by + threadIdx.y) * CHN + bx + threadIdx.x];
    __syncthreads();
    wt[(size_t)(bx + threadIdx.y) * CHN + by + threadIdx.x] = tile[threadIdx.x][threadIdx.y];
}

// ---------------- SGEMM, A K-major: C[m,n] = alpha*sum_k A[k*M+m]*B[k*N+n] (+bias[m]) (+res)
// scores_mode: skip tiles where key-frame > query-frame (block-causal)
__global__ __launch_bounds__(256) void sgemm_atk(
    const float* __restrict__ A, const float* __restrict__ B,
    float* __restrict__ C, const float* __restrict__ bias,
    const float* __restrict__ res, int M, int N, int K,
    float alpha, int scores_mode)
{
    int m0 = blockIdx.y * 128;
    int n0 = blockIdx.x * 128;
    if (scores_mode && ((n0 >> 10) > (m0 >> 10))) return;

    __shared__ float As[2][8][128];
    __shared__ float Bs[2][8][128];

    int tid = threadIdx.x;
    int lr = tid >> 5;            // 0..7
    int lc = (tid & 31) << 2;     // 0..124 step 4

    int nch = K >> 3;
    const float* Aptr = A + (size_t)lr * M + m0 + lc;
    const float* Bptr = B + (size_t)lr * N + n0 + lc;
    size_t sA = (size_t)8 * M;
    size_t sB = (size_t)8 * N;

    float4 fa = *(const float4*)Aptr;
    float4 fb = *(const float4*)Bptr;
    *(float4*)&As[0][lr][lc] = fa;
    *(float4*)&Bs[0][lr][lc] = fb;
    __syncthreads();

    float acc[8][8];
#pragma unroll
    for (int i = 0; i < 8; i++)
#pragma unroll
        for (int j = 0; j < 8; j++) acc[i][j] = 0.f;

    int tm = (tid >> 4) << 3;
    int tn = (tid & 15) << 3;
    int buf = 0;

    for (int kc = 0; kc < nch; kc++) {
        float4 na, nb;
        bool has = (kc + 1 < nch);
        if (has) {
            na = *(const float4*)(Aptr + (size_t)(kc + 1) * sA);
            nb = *(const float4*)(Bptr + (size_t)(kc + 1) * sB);
        }
#pragma unroll
        for (int kk = 0; kk < 8; kk++) {
            float4 a0 = *(float4*)&As[buf][kk][tm];
            float4 a1 = *(float4*)&As[buf][kk][tm + 4];
            float4 b0 = *(float4*)&Bs[buf][kk][tn];
            float4 b1 = *(float4*)&Bs[buf][kk][tn + 4];
            float av[8] = {a0.x,a0.y,a0.z,a0.w,a1.x,a1.y,a1.z,a1.w};
            float bv[8] = {b0.x,b0.y,b0.z,b0.w,b1.x,b1.y,b1.z,b1.w};
#pragma unroll
            for (int i = 0; i < 8; i++)
#pragma unroll
                for (int j = 0; j < 8; j++)
                    acc[i][j] += av[i] * bv[j];
        }
        if (has) {
            *(float4*)&As[buf ^ 1][lr][lc] = na;
            *(float4*)&Bs[buf ^ 1][lr][lc] = nb;
            __syncthreads();
            buf ^= 1;
        }
    }

#pragma unroll
    for (int i = 0; i < 8; i++) {
        int m = m0 + tm + i;
        float bs = bias ? bias[m] : 0.f;
        size_t off = (size_t)m * N + n0 + tn;
#pragma unroll
        for (int j = 0; j < 8; j++) {
            float v = acc[i][j] * alpha + bs;
            if (res) v += res[off + j];
            C[off + j] = v;
        }
    }
}

// ---------------- SGEMM NT: C[m,n] = sum_k A[m*K+k]*B[n*K+k]
// frame_limit: only accumulate k < ((n0>>10)+1)*1024  (block-causal prefix)
__global__ __launch_bounds__(256) void sgemm_nt(
    const float* __restrict__ A, const float* __restrict__ B,
    float* __restrict__ C, int M, int N, int K, int frame_limit)
{
    int m0 = blockIdx.y * 128;
    int n0 = blockIdx.x * 128;
    int Keff = frame_limit ? (((n0 >> 10) + 1) << 10) : K;
    int nch = Keff >> 3;

    __shared__ float As[2][8][128];
    __shared__ float Bs[2][8][128];

    int tid = threadIdx.x;
    int lm = tid >> 1;            // 0..127
    int lk = (tid & 1) << 2;      // 0 or 4

    const float* Aptr = A + (size_t)(m0 + lm) * K + lk;
    const float* Bptr = B + (size_t)(n0 + lm) * K + lk;

    float4 fa = *(const float4*)Aptr;
    float4 fb = *(const float4*)Bptr;
    As[0][lk + 0][lm] = fa.x; As[0][lk + 1][lm] = fa.y;
    As[0][lk + 2][lm] = fa.z; As[0][lk + 3][lm] = fa.w;
    Bs[0][lk + 0][lm] = fb.x; Bs[0][lk + 1][lm] = fb.y;
    Bs[0][lk + 2][lm] = fb.z; Bs[0][lk + 3][lm] = fb.w;
    __syncthreads();

    float acc[8][8];
#pragma unroll
    for (int i = 0; i < 8; i++)
#pragma unroll
        for (int j = 0; j < 8; j++) acc[i][j] = 0.f;

    int tm = (tid >> 4) << 3;
    int tn = (tid & 15) << 3;
    int buf = 0;

    for (int kc = 0; kc < nch; kc++) {
        float4 na, nb;
        bool has = (kc + 1 < nch);
        if (has) {
            na = *(const float4*)(Aptr + (size_t)(kc + 1) * 8);
            nb = *(const float4*)(Bptr + (size_t)(kc + 1) * 8);
        }
#pragma unroll
        for (int kk = 0; kk < 8; kk++) {
            float4 a0 = *(float4*)&As[buf][kk][tm];
            float4 a1 = *(float4*)&As[buf][kk][tm + 4];
            float4 b0 = *(float4*)&Bs[buf][kk][tn];
            float4 b1 = *(float4*)&Bs[buf][kk][tn + 4];
            float av[8] = {a0.x,a0.y,a0.z,a0.w,a1.x,a1.y,a1.z,a1.w};
            float bv[8] = {b0.x,b0.y,b0.z,b0.w,b1.x,b1.y,b1.z,b1.w};
#pragma unroll
            for (int i = 0; i < 8; i++)
#pragma unroll
                for (int j = 0; j < 8; j++)
                    acc[i][j] += av[i] * bv[j];
        }
        if (has) {
            As[buf ^ 1][lk + 0][lm] = na.x; As[buf ^ 1][lk + 1][lm] = na.y;
            As[buf ^ 1][lk + 2][lm] = na.z; As[buf ^ 1][lk + 3][lm] = na.w;
            Bs[buf ^ 1][lk + 0][lm] = nb.x; Bs[buf ^ 1][lk + 1][lm] = nb.y;
            Bs[buf ^ 1][lk + 2][lm] = nb.z; Bs[buf ^ 1][lk + 3][lm] = nb.w;
            __syncthreads();
            buf ^= 1;
        }
    }

#pragma unroll
    for (int i = 0; i < 8; i++) {
        size_t off = (size_t)(m0 + tm + i) * N + n0 + tn;
#pragma unroll
        for (int j = 0; j < 8; j++) C[off + j] = acc[i][j];
    }
}

// ---------------- conv3d 3x3x3 as tap-decomposed GEMM ----------------
// out[co,p] = sum_{tap,ci} wt[(tap*CHN+ci)*CHN+co] * xpad[ci*PLANE + boff(p) + dtap]
__global__ __launch_bounds__(256) void conv_kernel(
    const float* __restrict__ wt, const float* __restrict__ xp,
    const float* __restrict__ bias, const float* __restrict__ res,
    float* __restrict__ out)
{
    int m0 = blockIdx.y * 128;   // co
    int n0 = blockIdx.x * 128;   // spatial position
    __shared__ float As[2][8][128];
    __shared__ float Bs[2][8][128];
    __shared__ int boff[128];

    int tid = threadIdx.x;
    if (tid < 128) {
        int p = n0 + tid;
        int t = p >> 10;
        int r = p & 1023;
        int h = r >> 5;
        int w = r & 31;
        boff[tid] = t * (PHD * PWD) + h * PWD + w;
    }
    __syncthreads();

    int lr = tid >> 5;
    int lc = (tid & 31) << 2;

    // chunk index c in [0, 27*64): tap = c>>6, ci0 = (c&63)*8
    const int nch = 27 * 64;

    // initial load (chunk 0: tap 0, ci = lr)
    {
        float4 fa = *(const float4*)(wt + ((size_t)0 * CHN + lr) * CHN + m0 + lc);
        *(float4*)&As[0][lr][lc] = fa;
        const float* base = xp + (size_t)lr * PLANE;   // tap 0 -> dtap = 0
        Bs[0][lr][lc + 0] = base[boff[lc + 0]];
        Bs[0][lr][lc + 1] = base[boff[lc + 1]];
        Bs[0][lr][lc + 2] = base[boff[lc + 2]];
        Bs[0][lr][lc + 3] = base[boff[lc + 3]];
    }
    __syncthreads();

    float acc[8][8];
#pragma unroll
    for (int i = 0; i < 8; i++)
#pragma unroll
        for (int j = 0; j < 8; j++) acc[i][j] = 0.f;

    int tm = (tid >> 4) << 3;
    int tn = (tid & 15) << 3;
    int buf = 0;

    for (int kc = 0; kc < nch; kc++) {
        float4 na;
        float nb0, nb1, nb2, nb3;
        bool has = (kc + 1 < nch);
        if (has) {
            int c2 = kc + 1;
            int tap = c2 >> 6;
            int ci  = ((c2 & 63) << 3) + lr;
            na = *(const float4*)(wt + ((size_t)tap * CHN + ci) * CHN + m0 + lc);
            int kt = tap / 9, rr = tap % 9;
            int kh = rr / 3, kw = rr % 3;
            int d = kt * (PHD * PWD) + kh * PWD + kw;
            const float* base = xp + (size_t)ci * PLANE + d;
            nb0 = base[boff[lc + 0]];
            nb1 = base[boff[lc + 1]];
            nb2 = base[boff[lc + 2]];
            nb3 = base[boff[lc + 3]];
        }
#pragma unroll
        for (int kk = 0; kk < 8; kk++) {
            float4 a0 = *(float4*)&As[buf][kk][tm];
            float4 a1 = *(float4*)&As[buf][kk][tm + 4];
            float4 b0 = *(float4*)&Bs[buf][kk][tn];
            float4 b1 = *(float4*)&Bs[buf][kk][tn + 4];
            float av[8] = {a0.x,a0.y,a0.z,a0.w,a1.x,a1.y,a1.z,a1.w};
            float bv[8] = {b0.x,b0.y,b0.z,b0.w,b1.x,b1.y,b1.z,b1.w};
#pragma unroll
            for (int i = 0; i < 8; i++)
#pragma unroll
                for (int j = 0; j < 8; j++)
                    acc[i][j] += av[i] * bv[j];
        }
        if (has) {
            *(float4*)&As[buf ^ 1][lr][lc] = na;
            Bs[buf ^ 1][lr][lc + 0] = nb0;
            Bs[buf ^ 1][lr][lc + 1] = nb1;
            Bs[buf ^ 1][lr][lc + 2] = nb2;
            Bs[buf ^ 1][lr][lc + 3] = nb3;
            __syncthreads();
            buf ^= 1;
        }
    }

#pragma unroll
    for (int i = 0; i < 8; i++) {
        int m = m0 + tm + i;
        float bs = bias[m];
        size_t off = (size_t)m * SS + n0 + tn;
#pragma unroll
        for (int j = 0; j < 8; j++) {
            float v = acc[i][j] + bs;
            if (res) v += res[off + j];
            out[off + j] = v;
        }
    }
}

// ---------------- row softmax over allowed prefix ----------------
__global__ void softmax_kernel(float* __restrict__ P)
{
    int q = blockIdx.x;
    int limit = ((q >> 10) + 1) << 10;
    float* row = P + (size_t)q * SS;
    __shared__ float red[256];

    float m = -1e30f;
    for (int i = threadIdx.x; i < limit; i += 256) m = fmaxf(m, row[i]);
    red[threadIdx.x] = m;
    __syncthreads();
    for (int o = 128; o > 0; o >>= 1) {
        if (threadIdx.x < o) red[threadIdx.x] = fmaxf(red[threadIdx.x], red[threadIdx.x + o]);
        __syncthreads();
    }
    m = red[0];
    __syncthreads();

    float s = 0.f;
    for (int i = threadIdx.x; i < limit; i += 256) {
        float e = __expf(row[i] - m);
        row[i] = e;
        s += e;
    }
    red[threadIdx.x] = s;
    __syncthreads();
    for (int o = 128; o > 0; o >>= 1) {
        if (threadIdx.x < o) red[threadIdx.x] += red[threadIdx.x + o];
        __syncthreads();
    }
    float inv = 1.f / red[0];
    __syncthreads();
    for (int i = threadIdx.x; i < limit; i += 256) row[i] *= inv;
}

// ---------------- host ----------------
extern "C" void kernel_launch(void* const* d_in, const int* in_sizes, int n_in,
                              void* d_out, int out_size)
{
    const float* x = (const float*)d_in[0];
    // r0: 1..8, r1: 9..16
    const float* a_gns = (const float*)d_in[17];
    const float* a_gnb = (const float*)d_in[18];
    const float* a_wq  = (const float*)d_in[19];
    const float* a_bq  = (const float*)d_in[20];
    const float* a_wk  = (const float*)d_in[21];
    const float* a_bk  = (const float*)d_in[22];
    const float* a_wv  = (const float*)d_in[23];
    const float* a_bv  = (const float*)d_in[24];
    const float* a_wo  = (const float*)d_in[25];
    const float* a_bo  = (const float*)d_in[26];
    float* out = (float*)d_out;

    float *bufA, *bufB, *bufC, *bufD, *bufE, *padb, *P, *wt, *wl;
    cudaGetSymbolAddress((void**)&bufA, g_bufA);
    cudaGetSymbolAddress((void**)&bufB, g_bufB);
    cudaGetSymbolAddress((void**)&bufC, g_bufC);
    cudaGetSymbolAddress((void**)&bufD, g_bufD);
    cudaGetSymbolAddress((void**)&bufE, g_bufE);
    cudaGetSymbolAddress((void**)&padb, g_pad);
    cudaGetSymbolAddress((void**)&P,    g_P);
    cudaGetSymbolAddress((void**)&wt,   g_wt);
    cudaGetSymbolAddress((void**)&wl,   g_wl);

    const int padGrid = (CHN * PLANE + 255) / 256;
    const int rpGrid  = (27 * CHN * CHN + 255) / 256;
    dim3 gConv(64, 4);
    dim3 gScores(64, 64);
    dim3 gT(16, 16), bT(32, 32);

    // ---- resnet block helper (sequential stream ordering makes buffer reuse safe) ----
    auto resnet = [&](const float* in, const float* const* p, float* outbuf) {
        // p: n1s,n1b,w1,b1,n2s,n2b,w2,b2
        gn_kernel<<<32, 256>>>(in, p[0], p[1], bufA, 1);
        pad_kernel<<<padGrid, 256>>>(bufA, padb);
        repack_conv<<<rpGrid, 256>>>(p[2], wt);
        conv_kernel<<<gConv, 256>>>(wt, padb, p[3], nullptr, bufB);
        gn_kernel<<<32, 256>>>(bufB, p[4], p[5], bufA, 1);
        pad_kernel<<<padGrid, 256>>>(bufA, padb);
        repack_conv<<<rpGrid, 256>>>(p[6], wt);
        conv_kernel<<<gConv, 256>>>(wt, padb, p[7], in, outbuf);
    };

    const float* r0p[8] = {(const float*)d_in[1], (const float*)d_in[2],
                           (const float*)d_in[3], (const float*)d_in[4],
                           (const float*)d_in[5], (const float*)d_in[6],
                           (const float*)d_in[7], (const float*)d_in[8]};
    const float* r1p[8] = {(const float*)d_in[9],  (const float*)d_in[10],
                           (const float*)d_in[11], (const float*)d_in[12],
                           (const float*)d_in[13], (const float*)d_in[14],
                           (const float*)d_in[15], (const float*)d_in[16]};

    // ---- resnet 0: x -> bufC ----
    resnet(x, r0p, bufC);

    // ---- attention ----
    gn_kernel<<<32, 256>>>(bufC, a_gns, a_gnb, bufA, 0);   // xn in bufA

    transpose_lin<<<gT, bT>>>(a_wq, wl);
    sgemm_atk<<<gConv, 256>>>(wl, bufA, bufB, a_bq, nullptr, 512, 8192, 512, 1.f, 0); // Q
    transpose_lin<<<gT, bT>>>(a_wk, wl);
    sgemm_atk<<<gConv, 256>>>(wl, bufA, bufD, a_bk, nullptr, 512, 8192, 512, 1.f, 0); // K
    transpose_lin<<<gT, bT>>>(a_wv, wl);
    sgemm_atk<<<gConv, 256>>>(wl, bufA, bufE, a_bv, nullptr, 512, 8192, 512, 1.f, 0); // V

    // scores: P[q,k] = scale * sum_d Q[d,q]*K[d,k], masked tiles skipped
    sgemm_atk<<<gScores, 256>>>(bufB, bufD, P, nullptr, nullptr,
                                8192, 8192, 512, 0.044194173824159216f, 1);
    softmax_kernel<<<8192, 256>>>(P);

    // O[d,q] = sum_k V[d,k]*P[q,k]  (NT, K limited per query frame)
    sgemm_nt<<<gConv, 256>>>(bufE, P, bufA, 512, 8192, 8192, 1);

    // out-proj + bias + residual(bufC) -> bufD
    transpose_lin<<<gT, bT>>>(a_wo, wl);
    sgemm_atk<<<gConv, 256>>>(wl, bufA, bufD, a_bo, bufC, 512, 8192, 512, 1.f, 0);

    // ---- resnet 1: bufD -> d_out ----
    resnet(bufD, r1p, out);
}

// round 4
// speedup vs baseline: 2.1537x; 2.1537x over previous
#include <cuda_runtime.h>
#include <cuda_bf16.h>
#include <cstdint>

#define CHN 512
#define TT 8
#define HH 32
#define WW 32
#define SS 8192            // TT*HH*WW
#define PTD 10             // padded T (2 front)
#define PHD 34             // padded H
#define PWD 34             // padded W
#define PLANE (PTD*PHD*PWD)   // 11560
#define GN_GROUPS 32
#define GN_GSIZE 16        // CHN/GN_GROUPS
#define EPSV 1e-6f
#define KW 9               // smem row stride in 32-bit words (8 k-pairs + 1 pad, coprime to 32)

// ---------------- static scratch (no allocations allowed) ----------------
__device__ float g_bufA[CHN*SS];
__device__ float g_bufB[CHN*SS];
__device__ float g_bufC[CHN*SS];
__device__ float g_bufD[CHN*SS];
__device__ float g_bufE[CHN*SS];
__device__ float g_pad[CHN*PLANE];
__device__ float g_P[(size_t)SS*SS];        // 256 MB attention matrix
__device__ float g_wt[27*CHN*CHN];          // repacked conv weight [tap][ci][co]
__device__ float g_wl[CHN*CHN];             // transposed linear weight [c][o]

// ============================================================================
// bf16x3 MMA machinery
// ============================================================================

__device__ __forceinline__ void split2(float x0, float x1, uint32_t& hw, uint32_t& lw)
{
    __nv_bfloat162 h = __floats2bfloat162_rn(x0, x1);
    float r0 = x0 - __bfloat162float(h.x);
    float r1 = x1 - __bfloat162float(h.y);
    __nv_bfloat162 l = __floats2bfloat162_rn(r0, r1);
    hw = *(uint32_t*)&h;
    lw = *(uint32_t*)&l;
}

__device__ __forceinline__ void mma_bf16(float d[4], const uint32_t a[4], uint32_t b0, uint32_t b1)
{
    asm volatile(
        "mma.sync.aligned.m16n8k16.row.col.f32.bf16.bf16.f32 "
        "{%0,%1,%2,%3}, {%4,%5,%6,%7}, {%8,%9}, {%0,%1,%2,%3};"
        : "+f"(d[0]), "+f"(d[1]), "+f"(d[2]), "+f"(d[3])
        : "r"(a[0]), "r"(a[1]), "r"(a[2]), "r"(a[3]), "r"(b0), "r"(b1));
}

// One BK=16 step: warp tile 32(m) x 64(n); 3 products (hh, hl, lh) per output tile.
__device__ __forceinline__ void tile_compute(
    const uint32_t* __restrict__ Ah, const uint32_t* __restrict__ Al,
    const uint32_t* __restrict__ Bh, const uint32_t* __restrict__ Bl,
    float acc[2][8][4], int lane, int wm, int wn)
{
    int r = lane >> 2, c = lane & 3;
    uint32_t ah[2][4], al[2][4];
#pragma unroll
    for (int mt = 0; mt < 2; mt++) {
        int row = wm * 32 + mt * 16 + r;
        ah[mt][0] = Ah[row*KW + c];
        ah[mt][1] = Ah[(row+8)*KW + c];
        ah[mt][2] = Ah[row*KW + c + 4];
        ah[mt][3] = Ah[(row+8)*KW + c + 4];
        al[mt][0] = Al[row*KW + c];
        al[mt][1] = Al[(row+8)*KW + c];
        al[mt][2] = Al[row*KW + c + 4];
        al[mt][3] = Al[(row+8)*KW + c + 4];
    }
#pragma unroll
    for (int nt = 0; nt < 8; nt++) {
        int col = wn * 64 + nt * 8 + r;
        uint32_t bh0 = Bh[col*KW + c], bh1 = Bh[col*KW + c + 4];
        uint32_t bl0 = Bl[col*KW + c], bl1 = Bl[col*KW + c + 4];
#pragma unroll
        for (int mt = 0; mt < 2; mt++) {
            mma_bf16(acc[mt][nt], ah[mt], bh0, bh1);
            mma_bf16(acc[mt][nt], ah[mt], bl0, bl1);
            mma_bf16(acc[mt][nt], al[mt], bh0, bh1);
        }
    }
}

// ATK-style global load: G is k-major, G[k*ld + col]. Thread covers one column,
// 8 consecutive k. Coalesced across lanes (consecutive columns).
__device__ __forceinline__ void ldg_atk(const float* __restrict__ G, int ld,
                                        int colbase, int rowL, int kh, int k0, float v[8])
{
    const float* p = G + (size_t)(k0 + kh*8) * ld + colbase + rowL;
#pragma unroll
    for (int j = 0; j < 8; j++) v[j] = p[(size_t)j * ld];
}

// Conv gather load: B[k][n] = xp[ci*PLANE + off], k = tap*512 + ci.
__device__ __forceinline__ void ldg_conv(const float* __restrict__ xp,
                                         int cib, int off, int kh, float v[8])
{
    const float* p = xp + (size_t)(cib + kh*8) * PLANE + off;
#pragma unroll
    for (int j = 0; j < 8; j++) v[j] = p[(size_t)j * PLANE];
}

// Store 8 k-consecutive floats of one row as 4 hi + 4 lo packed bf16x2 words.
// Row stride KW=9 words => conflict-free STS across 32 consecutive rows.
__device__ __forceinline__ void sts8(const float v[8], uint32_t* Sh, uint32_t* Sl,
                                     int row, int kh)
{
#pragma unroll
    for (int jj = 0; jj < 4; jj++) {
        uint32_t hw, lw;
        split2(v[2*jj], v[2*jj+1], hw, lw);
        Sh[row*KW + kh*4 + jj] = hw;
        Sl[row*KW + kh*4 + jj] = lw;
    }
}

// NT-style load: G row-major [row*ld + k]; warp cooperatively loads 16 rows x 16 k.
__device__ __forceinline__ void ldg_nt(const float* __restrict__ G, int ld,
                                       int rowbase, int k0, int w, int lane, float2 v[4])
{
#pragma unroll
    for (int i = 0; i < 4; i++) {
        int row = w*16 + i*4 + (lane>>3);
        v[i] = *(const float2*)(G + (size_t)(rowbase + row)*ld + k0 + (lane&7)*2);
    }
}
__device__ __forceinline__ void sts_nt(const float2 v[4], uint32_t* Sh, uint32_t* Sl,
                                       int w, int lane)
{
#pragma unroll
    for (int i = 0; i < 4; i++) {
        int row = w*16 + i*4 + (lane>>3);
        uint32_t hw, lw;
        split2(v[i].x, v[i].y, hw, lw);
        Sh[row*KW + (lane&7)] = hw;
        Sl[row*KW + (lane&7)] = lw;
    }
}

// ============================================================================
// GEMM kernels (bf16x3 tensor-core)
// ============================================================================

// C[m,n] = alpha * sum_k A[k*M+m] * B[k*N+n] (+bias[m]) (+res)
// scores_mode: skip tiles where key-frame > query-frame (block-causal)
__global__ __launch_bounds__(256) void mma_atk(
    const float* __restrict__ A, const float* __restrict__ B,
    float* __restrict__ C, const float* __restrict__ bias,
    const float* __restrict__ res, int M, int N, int K,
    float alpha, int scores_mode)
{
    int m0 = blockIdx.y * 128;
    int n0 = blockIdx.x * 128;
    if (scores_mode && ((n0 >> 10) > (m0 >> 10))) return;

    __shared__ uint32_t sAh[2][128*KW], sAl[2][128*KW];
    __shared__ uint32_t sBh[2][128*KW], sBl[2][128*KW];

    int tid = threadIdx.x;
    int lane = tid & 31, w = tid >> 5;
    int wm = w >> 1, wn = w & 1;
    int rowL = tid & 127, kh = tid >> 7;

    int ns = K >> 4;
    float va[8], vb[8];

    ldg_atk(A, M, m0, rowL, kh, 0, va);
    ldg_atk(B, N, n0, rowL, kh, 0, vb);
    sts8(va, sAh[0], sAl[0], rowL, kh);
    sts8(vb, sBh[0], sBl[0], rowL, kh);
    __syncthreads();

    float acc[2][8][4];
#pragma unroll
    for (int i = 0; i < 2; i++)
#pragma unroll
        for (int j = 0; j < 8; j++)
#pragma unroll
            for (int k = 0; k < 4; k++) acc[i][j][k] = 0.f;

    int buf = 0;
    for (int s = 0; s < ns; s++) {
        bool has = (s + 1 < ns);
        if (has) {
            ldg_atk(A, M, m0, rowL, kh, (s+1)*16, va);
            ldg_atk(B, N, n0, rowL, kh, (s+1)*16, vb);
        }
        tile_compute(sAh[buf], sAl[buf], sBh[buf], sBl[buf], acc, lane, wm, wn);
        if (has) {
            sts8(va, sAh[buf^1], sAl[buf^1], rowL, kh);
            sts8(vb, sBh[buf^1], sBl[buf^1], rowL, kh);
            __syncthreads();
            buf ^= 1;
        }
    }

    int r = lane >> 2, c2 = (lane & 3) * 2;
#pragma unroll
    for (int mt = 0; mt < 2; mt++) {
#pragma unroll
        for (int half = 0; half < 2; half++) {
            int row = m0 + wm*32 + mt*16 + half*8 + r;
            float bs = bias ? bias[row] : 0.f;
            size_t ro = (size_t)row * N;
#pragma unroll
            for (int nt = 0; nt < 8; nt++) {
                int col = n0 + wn*64 + nt*8 + c2;
                float v0 = acc[mt][nt][half*2+0] * alpha + bs;
                float v1 = acc[mt][nt][half*2+1] * alpha + bs;
                if (res) { v0 += res[ro+col]; v1 += res[ro+col+1]; }
                C[ro+col] = v0; C[ro+col+1] = v1;
            }
        }
    }
}

// C[m,n] = sum_k A[m*K+k] * B[n*K+k]; frame_limit: k < ((n0>>10)+1)*1024
__global__ __launch_bounds__(256) void mma_nt(
    const float* __restrict__ A, const float* __restrict__ B,
    float* __restrict__ C, int M, int N, int K, int frame_limit)
{
    int m0 = blockIdx.y * 128;
    int n0 = blockIdx.x * 128;
    int Keff = frame_limit ? (((n0 >> 10) + 1) << 10) : K;
    int ns = Keff >> 4;

    __shared__ uint32_t sAh[2][128*KW], sAl[2][128*KW];
    __shared__ uint32_t sBh[2][128*KW], sBl[2][128*KW];

    int tid = threadIdx.x;
    int lane = tid & 31, w = tid >> 5;
    int wm = w >> 1, wn = w & 1;

    float2 va[4], vb[4];
    ldg_nt(A, K, m0, 0, w, lane, va);
    ldg_nt(B, K, n0, 0, w, lane, vb);
    sts_nt(va, sAh[0], sAl[0], w, lane);
    sts_nt(vb, sBh[0], sBl[0], w, lane);
    __syncthreads();

    float acc[2][8][4];
#pragma unroll
    for (int i = 0; i < 2; i++)
#pragma unroll
        for (int j = 0; j < 8; j++)
#pragma unroll
            for (int k = 0; k < 4; k++) acc[i][j][k] = 0.f;

    int buf = 0;
    for (int s = 0; s < ns; s++) {
        bool has = (s + 1 < ns);
        if (has) {
            ldg_nt(A, K, m0, (s+1)*16, w, lane, va);
            ldg_nt(B, K, n0, (s+1)*16, w, lane, vb);
        }
        tile_compute(sAh[buf], sAl[buf], sBh[buf], sBl[buf], acc, lane, wm, wn);
        if (has) {
            sts_nt(va, sAh[buf^1], sAl[buf^1], w, lane);
            sts_nt(vb, sBh[buf^1], sBl[buf^1], w, lane);
            __syncthreads();
            buf ^= 1;
        }
    }

    int r = lane >> 2, c2 = (lane & 3) * 2;
#pragma unroll
    for (int mt = 0; mt < 2; mt++) {
#pragma unroll
        for (int half = 0; half < 2; half++) {
            int row = m0 + wm*32 + mt*16 + half*8 + r;
            size_t ro = (size_t)row * N;
#pragma unroll
            for (int nt = 0; nt < 8; nt++) {
                int col = n0 + wn*64 + nt*8 + c2;
                C[ro+col]   = acc[mt][nt][half*2+0];
                C[ro+col+1] = acc[mt][nt][half*2+1];
            }
        }
    }
}

__device__ __forceinline__ int conv_dtap(int tap)
{
    int kt = tap / 9, rr = tap - kt*9;
    int kh3 = rr / 3, kw3 = rr - kh3*3;
    return kt * (PHD*PWD) + kh3 * PWD + kw3;
}

// conv3d 3x3x3 tap-decomposed GEMM on tensor cores
// out[co,p] = sum_{tap,ci} wt[(tap*CHN+ci)*CHN+co] * xpad[ci*PLANE + boff(p) + dtap]
__global__ __launch_bounds__(256) void mma_conv(
    const float* __restrict__ wt, const float* __restrict__ xp,
    const float* __restrict__ bias, const float* __restrict__ res,
    float* __restrict__ out)
{
    int m0 = blockIdx.y * 128;   // co
    int n0 = blockIdx.x * 128;   // spatial position

    __shared__ uint32_t sAh[2][128*KW], sAl[2][128*KW];
    __shared__ uint32_t sBh[2][128*KW], sBl[2][128*KW];
    __shared__ int boff[128];

    int tid = threadIdx.x;
    int lane = tid & 31, w = tid >> 5;
    int wm = w >> 1, wn = w & 1;
    int rowL = tid & 127, kh = tid >> 7;

    if (tid < 128) {
        int p = n0 + tid;
        int t = p >> 10;
        int rr = p & 1023;
        boff[tid] = t * (PHD*PWD) + (rr >> 5) * PWD + (rr & 31);
    }
    __syncthreads();
    int myoff = boff[rowL];

    const int ns = 27 * 32;   // 13824 / 16
    float va[8], vb[8];

    ldg_atk(wt, CHN, m0, rowL, kh, 0, va);
    ldg_conv(xp, 0, myoff + conv_dtap(0), kh, vb);
    sts8(va, sAh[0], sAl[0], rowL, kh);
    sts8(vb, sBh[0], sBl[0], rowL, kh);
    __syncthreads();

    float acc[2][8][4];
#pragma unroll
    for (int i = 0; i < 2; i++)
#pragma unroll
        for (int j = 0; j < 8; j++)
#pragma unroll
            for (int k = 0; k < 4; k++) acc[i][j][k] = 0.f;

    int buf = 0;
    for (int s = 0; s < ns; s++) {
        bool has = (s + 1 < ns);
        if (has) {
            int k0 = (s+1) * 16;
            int tap = k0 >> 9;
            int cib = k0 & 511;
            ldg_atk(wt, CHN, m0, rowL, kh, k0, va);
            ldg_conv(xp, cib, myoff + conv_dtap(tap), kh, vb);
        }
        tile_compute(sAh[buf], sAl[buf], sBh[buf], sBl[buf], acc, lane, wm, wn);
        if (has) {
            sts8(va, sAh[buf^1], sAl[buf^1], rowL, kh);
            sts8(vb, sBh[buf^1], sBl[buf^1], rowL, kh);
            __syncthreads();
            buf ^= 1;
        }
    }

    int r = lane >> 2, c2 = (lane & 3) * 2;
#pragma unroll
    for (int mt = 0; mt < 2; mt++) {
#pragma unroll
        for (int half = 0; half < 2; half++) {
            int row = m0 + wm*32 + mt*16 + half*8 + r;
            float bs = bias[row];
            size_t ro = (size_t)row * SS;
#pragma unroll
            for (int nt = 0; nt < 8; nt++) {
                int col = n0 + wn*64 + nt*8 + c2;
                float v0 = acc[mt][nt][half*2+0] + bs;
                float v1 = acc[mt][nt][half*2+1] + bs;
                if (res) { v0 += res[ro+col]; v1 += res[ro+col+1]; }
                out[ro+col] = v0; out[ro+col+1] = v1;
            }
        }
    }
}

// ============================================================================
// Elementwise / norm / pack kernels (unchanged from passing baseline)
// ============================================================================

__global__ void gn_kernel(const float* __restrict__ x, const float* __restrict__ sc,
                          const float* __restrict__ bi, float* __restrict__ y,
                          int do_silu)
{
    int g = blockIdx.x;
    const int n = GN_GSIZE * SS;
    const float* xg = x + (size_t)g * n;
    double s0 = 0.0, s1 = 0.0;
    for (int i = threadIdx.x; i < n; i += 256) {
        float v = xg[i];
        s0 += (double)v;
        s1 += (double)v * (double)v;
    }
    __shared__ double sh0[256], sh1[256];
    sh0[threadIdx.x] = s0; sh1[threadIdx.x] = s1;
    __syncthreads();
    for (int o = 128; o > 0; o >>= 1) {
        if (threadIdx.x < o) {
            sh0[threadIdx.x] += sh0[threadIdx.x + o];
            sh1[threadIdx.x] += sh1[threadIdx.x + o];
        }
        __syncthreads();
    }
    double mu = sh0[0] / n;
    double var = sh1[0] / n - mu * mu;
    float mean = (float)mu;
    float rstd = rsqrtf((float)var + EPSV);
    float* yg = y + (size_t)g * n;
    for (int i = threadIdx.x; i < n; i += 256) {
        int c = g * GN_GSIZE + (i >> 13);
        float v = (xg[i] - mean) * rstd * sc[c] + bi[c];
        if (do_silu) v = v / (1.f + __expf(-v));
        yg[i] = v;
    }
}

__global__ void pad_kernel(const float* __restrict__ x, float* __restrict__ xp)
{
    int idx = blockIdx.x * blockDim.x + threadIdx.x;
    const int total = CHN * PLANE;
    if (idx >= total) return;
    int c  = idx / PLANE;
    int r  = idx % PLANE;
    int tp = r / (PHD * PWD);
    int r2 = r % (PHD * PWD);
    int hp = r2 / PWD;
    int wp = r2 % PWD;
    int t = tp - 2; if (t < 0) t = 0; if (t > TT-1) t = TT-1;
    int h = hp - 1; if (h < 0) h = 0; if (h > HH-1) h = HH-1;
    int w = wp - 1; if (w < 0) w = 0; if (w > WW-1) w = WW-1;
    xp[idx] = x[((size_t)(c * TT + t) * HH + h) * WW + w];
}

__global__ void repack_conv(const float* __restrict__ w, float* __restrict__ wt)
{
    int idx = blockIdx.x * blockDim.x + threadIdx.x;
    const int total = 27 * CHN * CHN;
    if (idx >= total) return;
    int co = idx % CHN;
    int r  = idx / CHN;
    int ci = r % CHN;
    int k  = r / CHN;
    wt[idx] = w[((size_t)co * CHN + ci) * 27 + k];
}

__global__ void transpose_lin(const float* __restrict__ w, float* __restrict__ wt)
{
    __shared__ float tile[32][33];
    int bx = blockIdx.x * 32, by = blockIdx.y * 32;
    tile[threadIdx.y][threadIdx.x] = w[(size_t)(by + threadIdx.y) * CHN + bx + threadIdx.x];
    __syncthreads();
    wt[(size_t)(bx + threadIdx.y) * CHN + by + threadIdx.x] = tile[threadIdx.x][threadIdx.y];
}

__global__ void softmax_kernel(float* __restrict__ P)
{
    int q = blockIdx.x;
    int limit = ((q >> 10) + 1) << 10;
    float* row = P + (size_t)q * SS;
    __shared__ float red[256];

    float m = -1e30f;
    for (int i = threadIdx.x; i < limit; i += 256) m = fmaxf(m, row[i]);
    red[threadIdx.x] = m;
    __syncthreads();
    for (int o = 128; o > 0; o >>= 1) {
        if (threadIdx.x < o) red[threadIdx.x] = fmaxf(red[threadIdx.x], red[threadIdx.x + o]);
        __syncthreads();
    }
    m = red[0];
    __syncthreads();

    float s = 0.f;
    for (int i = threadIdx.x; i < limit; i += 256) {
        float e = __expf(row[i] - m);
        row[i] = e;
        s += e;
    }
    red[threadIdx.x] = s;
    __syncthreads();
    for (int o = 128; o > 0; o >>= 1) {
        if (threadIdx.x < o) red[threadIdx.x] += red[threadIdx.x + o];
        __syncthreads();
    }
    float inv = 1.f / red[0];
    __syncthreads();
    for (int i = threadIdx.x; i < limit; i += 256) row[i] *= inv;
}

// ---------------- host ----------------
extern "C" void kernel_launch(void* const* d_in, const int* in_sizes, int n_in,
                              void* d_out, int out_size)
{
    const float* x = (const float*)d_in[0];
    const float* a_gns = (const float*)d_in[17];
    const float* a_gnb = (const float*)d_in[18];
    const float* a_wq  = (const float*)d_in[19];
    const float* a_bq  = (const float*)d_in[20];
    const float* a_wk  = (const float*)d_in[21];
    const float* a_bk  = (const float*)d_in[22];
    const float* a_wv  = (const float*)d_in[23];
    const float* a_bv  = (const float*)d_in[24];
    const float* a_wo  = (const float*)d_in[25];
    const float* a_bo  = (const float*)d_in[26];
    float* out = (float*)d_out;

    float *bufA, *bufB, *bufC, *bufD, *bufE, *padb, *P, *wt, *wl;
    cudaGetSymbolAddress((void**)&bufA, g_bufA);
    cudaGetSymbolAddress((void**)&bufB, g_bufB);
    cudaGetSymbolAddress((void**)&bufC, g_bufC);
    cudaGetSymbolAddress((void**)&bufD, g_bufD);
    cudaGetSymbolAddress((void**)&bufE, g_bufE);
    cudaGetSymbolAddress((void**)&padb, g_pad);
    cudaGetSymbolAddress((void**)&P,    g_P);
    cudaGetSymbolAddress((void**)&wt,   g_wt);
    cudaGetSymbolAddress((void**)&wl,   g_wl);

    const int padGrid = (CHN * PLANE + 255) / 256;
    const int rpGrid  = (27 * CHN * CHN + 255) / 256;
    dim3 gConv(64, 4);
    dim3 gScores(64, 64);
    dim3 gT(16, 16), bT(32, 32);

    auto resnet = [&](const float* in, const float* const* p, float* outbuf) {
        gn_kernel<<<32, 256>>>(in, p[0], p[1], bufA, 1);
        pad_kernel<<<padGrid, 256>>>(bufA, padb);
        repack_conv<<<rpGrid, 256>>>(p[2], wt);
        mma_conv<<<gConv, 256>>>(wt, padb, p[3], nullptr, bufB);
        gn_kernel<<<32, 256>>>(bufB, p[4], p[5], bufA, 1);
        pad_kernel<<<padGrid, 256>>>(bufA, padb);
        repack_conv<<<rpGrid, 256>>>(p[6], wt);
        mma_conv<<<gConv, 256>>>(wt, padb, p[7], in, outbuf);
    };

    const float* r0p[8] = {(const float*)d_in[1], (const float*)d_in[2],
                           (const float*)d_in[3], (const float*)d_in[4],
                           (const float*)d_in[5], (const float*)d_in[6],
                           (const float*)d_in[7], (const float*)d_in[8]};
    const float* r1p[8] = {(const float*)d_in[9],  (const float*)d_in[10],
                           (const float*)d_in[11], (const float*)d_in[12],
                           (const float*)d_in[13], (const float*)d_in[14],
                           (const float*)d_in[15], (const float*)d_in[16]};

    // ---- resnet 0: x -> bufC ----
    resnet(x, r0p, bufC);

    // ---- attention ----
    gn_kernel<<<32, 256>>>(bufC, a_gns, a_gnb, bufA, 0);   // xn in bufA

    transpose_lin<<<gT, bT>>>(a_wq, wl);
    mma_atk<<<gConv, 256>>>(wl, bufA, bufB, a_bq, nullptr, 512, 8192, 512, 1.f, 0); // Q
    transpose_lin<<<gT, bT>>>(a_wk, wl);
    mma_atk<<<gConv, 256>>>(wl, bufA, bufD, a_bk, nullptr, 512, 8192, 512, 1.f, 0); // K
    transpose_lin<<<gT, bT>>>(a_wv, wl);
    mma_atk<<<gConv, 256>>>(wl, bufA, bufE, a_bv, nullptr, 512, 8192, 512, 1.f, 0); // V

    // scores: P[q,k] = scale * sum_d Q[d,q]*K[d,k], masked tiles skipped
    mma_atk<<<gScores, 256>>>(bufB, bufD, P, nullptr, nullptr,
                              8192, 8192, 512, 0.044194173824159216f, 1);
    softmax_kernel<<<8192, 256>>>(P);

    // O[d,q] = sum_k V[d,k]*P[q,k]  (NT, K limited per query frame)
    mma_nt<<<gConv, 256>>>(bufE, P, bufA, 512, 8192, 8192, 1);

    // out-proj + bias + residual(bufC) -> bufD
    transpose_lin<<<gT, bT>>>(a_wo, wl);
    mma_atk<<<gConv, 256>>>(wl, bufA, bufD, a_bo, bufC, 512, 8192, 512, 1.f, 0);

    // ---- resnet 1: bufD -> d_out ----
    resnet(bufD, r1p, out);
}